// round 5
// baseline (speedup 1.0000x reference)
#include <cuda_runtime.h>

// ---------------------------------------------------------------------------
// Problem constants
// ---------------------------------------------------------------------------
constexpr int TFR   = 65536;
constexpr int KB9   = 9;
constexpr int BATCH = 32;
constexpr int LOUT  = (TFR - 1) * 4;            // 262140

constexpr int OT   = 1000;                      // output samples per tile
constexpr int NT   = (LOUT + OT - 1) / OT;      // 263 tiles
constexpr int NTHR = 256;

// Shared layout (word offsets). Even/odd row split; E->O base deltas are
// == 16 (mod 32 words) so mixed-parity access patterns stay conflict-free.
constexpr int OFF_MCE = 0;                       // mag rows even: 130 x 12
constexpr int OFF_MCO = 1584;                    // mag rows odd:  130 x 12
constexpr int OFF_WVE = 3144;                    // wav groups even: 128 x 4
constexpr int OFF_WVO = 3656;                    // wav groups odd:  128 x 4
constexpr int OFF_SPE = 4168;                    // P rows even: 127 x 20
constexpr int OFF_SPO = 6744;                    // P rows odd:  126 x 20
constexpr int SMWORDS = 9280;                    // 37120 bytes

// ---------------------------------------------------------------------------
// Compile-time twiddles (all angles multiples of pi/8)
// ---------------------------------------------------------------------------
#define HD __host__ __device__ __forceinline__

HD constexpr float cos8c(int m) {
    m &= 15;
    const int mm = m & 7;
    const float v =
        (mm == 0) ?  1.0f :
        (mm == 1) ?  0.92387953251128674f :
        (mm == 2) ?  0.70710678118654752f :
        (mm == 3) ?  0.38268343236508977f :
        (mm == 4) ?  0.0f :
        (mm == 5) ? -0.38268343236508977f :
        (mm == 6) ? -0.70710678118654752f :
                    -0.92387953251128674f;
    return (m & 8) ? -v : v;
}
HD constexpr float sin8c(int m) { return cos8c(m + 12); }
HD constexpr float wwinc(int n) { return 0.5f - 0.5f * cos8c(n); }   // hann(16)
HD constexpr float CSc(int k, int n) { return ((k == 0) ? 1.0f : 2.0f) * 0.0625f * cos8c(k * n) * wwinc(n); }
HD constexpr float SNc(int k, int n) { return -2.0f * 0.0625f * sin8c(k * n) * wwinc(n); }
HD constexpr float envsum(int r) {
    return wwinc(r)      * wwinc(r)      + wwinc(r + 4)  * wwinc(r + 4)
         + wwinc(r + 8)  * wwinc(r + 8)  + wwinc(r + 12) * wwinc(r + 12);
}
HD constexpr float EINVc(int r) { return 1.0f / envsum(r); }
// env-folded coefficients (phase A fast path only)
HD constexpr float CSF(int k, int n) { return CSc(k, n) * EINVc(n & 3); }

// Runtime tables for rare edge-fallback paths
__constant__ float C8T[16] = { cos8c(0), cos8c(1), cos8c(2), cos8c(3), cos8c(4), cos8c(5), cos8c(6), cos8c(7),
                               cos8c(8), cos8c(9), cos8c(10), cos8c(11), cos8c(12), cos8c(13), cos8c(14), cos8c(15) };
__constant__ float W16T[16] = { wwinc(0), wwinc(1), wwinc(2), wwinc(3), wwinc(4), wwinc(5), wwinc(6), wwinc(7),
                                wwinc(8), wwinc(9), wwinc(10), wwinc(11), wwinc(12), wwinc(13), wwinc(14), wwinc(15) };

// ---------------------------------------------------------------------------
// Row-pointer helpers (even/odd split)
// ---------------------------------------------------------------------------
__device__ __forceinline__ float* magRowPtr(float* sm, int r) {
    return sm + (r >> 1) * 12 + ((r & 1) ? OFF_MCO : OFF_MCE);
}
__device__ __forceinline__ float* pRowPtr(float* sm, int r) {
    return sm + (r >> 1) * 20 + ((r & 1) ? OFF_SPO : OFF_SPE);
}
__device__ __forceinline__ float* wavPtr(float* sm, int g) {
    return sm + (g >> 1) * 4 + ((g & 1) ? OFF_WVO : OFF_WVE);
}

// ---------------------------------------------------------------------------
// Phase-A accumulator (env folded in; fully constant-folded)
// ---------------------------------------------------------------------------
template<int JJ>
__device__ __forceinline__ void accA(const float4 u0, const float4 u1, const float m4,
                                     float& y0, float& y1, float& y2, float& y3)
{
    { constexpr int n = 4 * JJ + 0;
      if (CSF(0,n) != 0.f) y0 = fmaf(u0.x, CSF(0,n), y0);
      if (CSF(1,n) != 0.f) y0 = fmaf(u0.y, CSF(1,n), y0);
      if (CSF(2,n) != 0.f) y0 = fmaf(u0.z, CSF(2,n), y0);
      if (CSF(3,n) != 0.f) y0 = fmaf(u0.w, CSF(3,n), y0);
      if (CSF(4,n) != 0.f) y0 = fmaf(m4,   CSF(4,n), y0); }
    { constexpr int n = 4 * JJ + 1;
      if (CSF(0,n) != 0.f) y1 = fmaf(u1.x, CSF(0,n), y1);
      if (CSF(1,n) != 0.f) y1 = fmaf(u1.y, CSF(1,n), y1);
      if (CSF(2,n) != 0.f) y1 = fmaf(u1.z, CSF(2,n), y1);
      if (CSF(3,n) != 0.f) y1 = fmaf(u1.w, CSF(3,n), y1); }
    { constexpr int n = 4 * JJ + 2;
      if (CSF(0,n) != 0.f) y2 = fmaf(u0.x, CSF(0,n), y2);
      if (CSF(1,n) != 0.f) y2 = fmaf(u0.y, CSF(1,n), y2);
      if (CSF(2,n) != 0.f) y2 = fmaf(u0.z, CSF(2,n), y2);
      if (CSF(3,n) != 0.f) y2 = fmaf(u0.w, CSF(3,n), y2);
      if (CSF(4,n) != 0.f) y2 = fmaf(m4,   CSF(4,n), y2); }
    { constexpr int n = 4 * JJ + 3;
      if (CSF(0,n) != 0.f) y3 = fmaf(u1.x, CSF(0,n), y3);
      if (CSF(1,n) != 0.f) y3 = fmaf(u1.y, CSF(1,n), y3);
      if (CSF(2,n) != 0.f) y3 = fmaf(u1.z, CSF(2,n), y3);
      if (CSF(3,n) != 0.f) y3 = fmaf(u1.w, CSF(3,n), y3); }
}

// P accumulator: per-frame windowed ISTFT samples, NO env folding.
template<int JJ>
__device__ __forceinline__ void accP(const float4 v0, const float4 v1, const float4 v2, const float4 v3,
                                     float& y0, float& y1, float& y2, float& y3)
{
    { constexpr int n = 4 * JJ + 0;
      if (CSc(0,n) != 0.f) y0 = fmaf(v0.x, CSc(0,n), y0);
      if (CSc(1,n) != 0.f) y0 = fmaf(v0.y, CSc(1,n), y0);
      if (CSc(2,n) != 0.f) y0 = fmaf(v0.z, CSc(2,n), y0);
      if (CSc(3,n) != 0.f) y0 = fmaf(v0.w, CSc(3,n), y0);
      if (CSc(4,n) != 0.f) y0 = fmaf(v3.w, CSc(4,n), y0);
      if (SNc(1,n) != 0.f) y0 = fmaf(v3.x, SNc(1,n), y0);
      if (SNc(2,n) != 0.f) y0 = fmaf(v3.y, SNc(2,n), y0);
      if (SNc(3,n) != 0.f) y0 = fmaf(v3.z, SNc(3,n), y0); }
    { constexpr int n = 4 * JJ + 1;
      if (CSc(0,n) != 0.f) y1 = fmaf(v1.x, CSc(0,n), y1);
      if (CSc(1,n) != 0.f) y1 = fmaf(v1.y, CSc(1,n), y1);
      if (CSc(2,n) != 0.f) y1 = fmaf(v1.z, CSc(2,n), y1);
      if (CSc(3,n) != 0.f) y1 = fmaf(v1.w, CSc(3,n), y1);
      if (SNc(1,n) != 0.f) y1 = fmaf(v2.x, SNc(1,n), y1);
      if (SNc(2,n) != 0.f) y1 = fmaf(v2.y, SNc(2,n), y1);
      if (SNc(3,n) != 0.f) y1 = fmaf(v2.z, SNc(3,n), y1);
      if (SNc(4,n) != 0.f) y1 = fmaf(v2.w, SNc(4,n), y1); }
    { constexpr int n = 4 * JJ + 2;
      if (CSc(0,n) != 0.f) y2 = fmaf(v0.x, CSc(0,n), y2);
      if (CSc(1,n) != 0.f) y2 = fmaf(v0.y, CSc(1,n), y2);
      if (CSc(2,n) != 0.f) y2 = fmaf(v0.z, CSc(2,n), y2);
      if (CSc(3,n) != 0.f) y2 = fmaf(v0.w, CSc(3,n), y2);
      if (CSc(4,n) != 0.f) y2 = fmaf(v3.w, CSc(4,n), y2);
      if (SNc(1,n) != 0.f) y2 = fmaf(v3.x, SNc(1,n), y2);
      if (SNc(2,n) != 0.f) y2 = fmaf(v3.y, SNc(2,n), y2);
      if (SNc(3,n) != 0.f) y2 = fmaf(v3.z, SNc(3,n), y2); }
    { constexpr int n = 4 * JJ + 3;
      if (CSc(0,n) != 0.f) y3 = fmaf(v1.x, CSc(0,n), y3);
      if (CSc(1,n) != 0.f) y3 = fmaf(v1.y, CSc(1,n), y3);
      if (CSc(2,n) != 0.f) y3 = fmaf(v1.z, CSc(2,n), y3);
      if (CSc(3,n) != 0.f) y3 = fmaf(v1.w, CSc(3,n), y3);
      if (SNc(1,n) != 0.f) y3 = fmaf(v2.x, SNc(1,n), y3);
      if (SNc(2,n) != 0.f) y3 = fmaf(v2.y, SNc(2,n), y3);
      if (SNc(3,n) != 0.f) y3 = fmaf(v2.z, SNc(3,n), y3);
      if (SNc(4,n) != 0.f) y3 = fmaf(v2.w, SNc(4,n), y3); }
}

// ---------------------------------------------------------------------------
// B1 frame processing: rfft fold + phase-normalize + frame ISTFT -> P row.
// A0..A3 = 16 wav samples of this frame; mrp = staged mag row (S/D/m4).
// ---------------------------------------------------------------------------
__device__ __forceinline__ void processFrame(const float4 A0, const float4 A1,
                                             const float4 A2, const float4 A3,
                                             const float* __restrict__ mrp,
                                             float* __restrict__ prow)
{
    const float x1 = A0.y, x2 = A0.z, x3 = A0.w, x4 = A1.x, x5 = A1.y, x6 = A1.z, x7 = A1.w;
    const float x8 = A2.x, x9 = A2.y, x10 = A2.z, x11 = A2.w, x12 = A3.x, x13 = A3.y, x14 = A3.z, x15 = A3.w;

    float e[8], o[8];
    e[1] = wwinc(1) * (x1 + x15);  o[1] = wwinc(1) * (x1 - x15);
    e[2] = wwinc(2) * (x2 + x14);  o[2] = wwinc(2) * (x2 - x14);
    e[3] = wwinc(3) * (x3 + x13);  o[3] = wwinc(3) * (x3 - x13);
    e[4] = wwinc(4) * (x4 + x12);  o[4] = wwinc(4) * (x4 - x12);
    e[5] = wwinc(5) * (x5 + x11);  o[5] = wwinc(5) * (x5 - x11);
    e[6] = wwinc(6) * (x6 + x10);  o[6] = wwinc(6) * (x6 - x10);
    e[7] = wwinc(7) * (x7 + x9);   o[7] = wwinc(7) * (x7 - x9);

    // Magnitudes reconstructed from staged S/D
    const float4 MS = *reinterpret_cast<const float4*>(mrp);
    const float4 MD = *reinterpret_cast<const float4*>(mrp + 4);
    float mv[9];
    mv[0] = 0.5f * (MS.x + MD.x);  mv[8] = 0.5f * (MS.x - MD.x);
    mv[1] = 0.5f * (MS.y + MD.y);  mv[7] = 0.5f * (MS.y - MD.y);
    mv[2] = 0.5f * (MS.z + MD.z);  mv[6] = 0.5f * (MS.z - MD.z);
    mv[3] = 0.5f * (MS.w + MD.w);  mv[5] = 0.5f * (MS.w - MD.w);
    mv[4] = mrp[8];

    float ca[9], sa[9];
    #pragma unroll
    for (int k = 0; k < 9; k++) {
        float re = (k & 1) ? -x8 : x8;
        #pragma unroll
        for (int n = 1; n < 8; n++) {
            const float c = cos8c(k * n);
            if (c != 0.f) re = fmaf(e[n], c, re);
        }
        if (k == 0 || k == 8) {
            ca[k] = copysignf(mv[k], re);
            sa[k] = 0.f;
        } else {
            float im = 0.f;
            #pragma unroll
            for (int n = 1; n < 8; n++) {
                const float ns = -sin8c(k * n);
                if (ns != 0.f) im = fmaf(o[n], ns, im);
            }
            const float n2 = fmaf(re, re, im * im);
            if (n2 > 0.f) {
                const float u = mv[k] * rsqrtf(n2);
                ca[k] = re * u;
                sa[k] = im * u;
            } else {
                ca[k] = mv[k];
                sa[k] = 0.f;
            }
        }
    }

    // Symmetric combos, then full 16-sample windowed frame ISTFT
    const float4 v0 = make_float4(ca[0] + ca[8], ca[1] + ca[7], ca[2] + ca[6], ca[3] + ca[5]);
    const float4 v1 = make_float4(ca[0] - ca[8], ca[1] - ca[7], ca[2] - ca[6], ca[3] - ca[5]);
    const float4 v2 = make_float4(sa[1] + sa[7], sa[2] + sa[6], sa[3] + sa[5], sa[4]);
    const float4 v3 = make_float4(sa[1] - sa[7], sa[2] - sa[6], sa[3] - sa[5], ca[4]);

    float p00 = 0.f, p01 = 0.f, p02 = 0.f, p03 = 0.f;
    float p10 = 0.f, p11 = 0.f, p12 = 0.f, p13 = 0.f;
    float p20 = 0.f, p21 = 0.f, p22 = 0.f, p23 = 0.f;
    float p30 = 0.f, p31 = 0.f, p32 = 0.f, p33 = 0.f;
    accP<0>(v0, v1, v2, v3, p00, p01, p02, p03);
    accP<1>(v0, v1, v2, v3, p10, p11, p12, p13);
    accP<2>(v0, v1, v2, v3, p20, p21, p22, p23);
    accP<3>(v0, v1, v2, v3, p30, p31, p32, p33);

    *reinterpret_cast<float4*>(prow)      = make_float4(p00, p01, p02, p03);
    *reinterpret_cast<float4*>(prow + 4)  = make_float4(p10, p11, p12, p13);
    *reinterpret_cast<float4*>(prow + 8)  = make_float4(p20, p21, p22, p23);
    *reinterpret_cast<float4*>(prow + 12) = make_float4(p30, p31, p32, p33);
}

// ---------------------------------------------------------------------------
__global__ void __launch_bounds__(NTHR)
glim_kernel(const float* __restrict__ mag, float* __restrict__ out)
{
    __shared__ __align__(16) float sm[SMWORDS];

    const int tid  = threadIdx.x;
    const int b    = blockIdx.y;
    const int s0   = blockIdx.x * OT;
    const int nout = min(OT, LOUT - s0);
    const int F0   = s0 >> 2;
    const int TLO  = max(0, F0 - 1);
    const int THI  = min(TFR - 1, (s0 + nout + 7) >> 2);
    const int NFR  = THI - TLO + 1;
    const int tM0  = TLO - 3;
    const int ROWS = NFR + 7;

    const float* magb = mag + (size_t)b * (KB9 * TFR);

    // ---- stage: load bin pairs, store combined S/D + M4 ----
    #pragma unroll
    for (int pass = 0; pass < 2; pass++) {
        const int tt = tid + pass * NTHR;
        if (tt < ROWS) {
            const int tg = tM0 + tt;
            float4 S, D; float m4;
            if (tg >= 0 && tg < TFR) {
                const float* gp = magb + tg;
                const float a0 = __ldg(gp);            const float a8 = __ldg(gp + 8 * TFR);
                const float a1 = __ldg(gp + 1 * TFR);  const float a7 = __ldg(gp + 7 * TFR);
                const float a2 = __ldg(gp + 2 * TFR);  const float a6 = __ldg(gp + 6 * TFR);
                const float a3 = __ldg(gp + 3 * TFR);  const float a5 = __ldg(gp + 5 * TFR);
                m4 = __ldg(gp + 4 * TFR);
                S = make_float4(a0 + a8, a1 + a7, a2 + a6, a3 + a5);
                D = make_float4(a0 - a8, a1 - a7, a2 - a6, a3 - a5);
            } else {
                S = make_float4(0.f, 0.f, 0.f, 0.f);
                D = S; m4 = 0.f;
            }
            float* rp = magRowPtr(sm, tt);
            *reinterpret_cast<float4*>(rp)     = S;
            *reinterpret_cast<float4*>(rp + 4) = D;
            rp[8] = m4;
        }
    }
    __syncthreads();

    // ---- Phase A (paired): wav_i = ISTFT of zero-phase spectrum ----
    const int ngA = NFR + 3;
    const int npA = (ngA + 1) >> 1;
    if (tid < npA) {
        const int t  = tid;
        const int g0 = 2 * t;
        const int g1 = g0 + 1;
        const int jb0 = 4 * TLO - 8 + 4 * g0;
        const int X0  = TLO + g0;
        const bool fast = (g1 < ngA) && (jb0 >= 0) && (jb0 + 7 < LOUT) &&
                          (X0 >= 3) && (X0 + 1 <= TFR - 1);
        if (fast) {
            float y00 = 0.f, y01 = 0.f, y02 = 0.f, y03 = 0.f;
            float y10 = 0.f, y11 = 0.f, y12 = 0.f, y13 = 0.f;
            const float* rE = sm + OFF_MCE + t * 12;
            const float* rO = sm + OFF_MCO + t * 12;
            {   const float4 u0 = *reinterpret_cast<const float4*>(rE);
                const float4 u1 = *reinterpret_cast<const float4*>(rE + 4);
                const float  m4 = rE[8];
                accA<3>(u0, u1, m4, y00, y01, y02, y03); }
            {   const float4 u0 = *reinterpret_cast<const float4*>(rO);
                const float4 u1 = *reinterpret_cast<const float4*>(rO + 4);
                const float  m4 = rO[8];
                accA<2>(u0, u1, m4, y00, y01, y02, y03);
                accA<3>(u0, u1, m4, y10, y11, y12, y13); }
            {   const float4 u0 = *reinterpret_cast<const float4*>(rE + 12);
                const float4 u1 = *reinterpret_cast<const float4*>(rE + 16);
                const float  m4 = rE[20];
                accA<1>(u0, u1, m4, y00, y01, y02, y03);
                accA<2>(u0, u1, m4, y10, y11, y12, y13); }
            {   const float4 u0 = *reinterpret_cast<const float4*>(rO + 12);
                const float4 u1 = *reinterpret_cast<const float4*>(rO + 16);
                const float  m4 = rO[20];
                accA<0>(u0, u1, m4, y00, y01, y02, y03);
                accA<1>(u0, u1, m4, y10, y11, y12, y13); }
            {   const float4 u0 = *reinterpret_cast<const float4*>(rE + 24);
                const float4 u1 = *reinterpret_cast<const float4*>(rE + 28);
                const float  m4 = rE[32];
                accA<0>(u0, u1, m4, y10, y11, y12, y13); }
            *reinterpret_cast<float4*>(sm + OFF_WVE + t * 4) = make_float4(y00, y01, y02, y03);
            *reinterpret_cast<float4*>(sm + OFF_WVO + t * 4) = make_float4(y10, y11, y12, y13);
        } else {
            for (int gi = 0; gi < 2; gi++) {
                const int g = g0 + gi;
                if (g >= ngA) break;
                const int jbase = 4 * TLO - 8 + 4 * g;
                float* wp = wavPtr(sm, g);
                for (int r = 0; r < 4; r++) {
                    const int jg = jbase + r;
                    const int jr = (jg < 0) ? -jg : ((jg >= LOUT) ? 2 * LOUT - 2 - jg : jg);
                    const int p  = jr + 8;
                    const int Xp = p >> 2;
                    const int rr = p & 3;
                    float acc = 0.f, env = 0.f;
                    for (int jj = 0; jj < 4; jj++) {
                        const int tt = Xp - jj;
                        if (tt < 0 || tt >= TFR) continue;
                        const int n = rr + 4 * jj;
                        const float w = W16T[n];
                        const float* rp = magRowPtr(sm, tt - tM0);
                        float ssum;
                        if (n & 1) {
                            ssum = rp[4]
                                 + 2.f * (rp[5] * C8T[n & 15] + rp[6] * C8T[(2 * n) & 15] + rp[7] * C8T[(3 * n) & 15]);
                        } else {
                            ssum = rp[0]
                                 + 2.f * (rp[1] * C8T[n & 15] + rp[2] * C8T[(2 * n) & 15] + rp[3] * C8T[(3 * n) & 15]
                                        + rp[8] * C8T[(4 * n) & 15]);
                        }
                        acc = fmaf(ssum, 0.0625f * w, acc);
                        env = fmaf(w, w, env);
                    }
                    wp[r] = acc / env;
                }
            }
        }
    }
    __syncthreads();

    // ---- Phase B1 (paired): rfft + normalize + frame ISTFT -> P rows ----
    const int npB = (NFR + 1) >> 1;
    if (tid < npB) {
        const int t  = tid;
        const int f0 = 2 * t;
        const int f1 = f0 + 1;
        // wav groups f0..f0+4 -> E rows t,t+1,t+2 ; O rows t,t+1
        const float4 E0 = *reinterpret_cast<const float4*>(sm + OFF_WVE + t * 4);
        const float4 O0 = *reinterpret_cast<const float4*>(sm + OFF_WVO + t * 4);
        const float4 E1 = *reinterpret_cast<const float4*>(sm + OFF_WVE + (t + 1) * 4);
        const float4 O1 = *reinterpret_cast<const float4*>(sm + OFF_WVO + (t + 1) * 4);
        // frame f0: groups f0..f0+3 = E t, O t, E t+1, O t+1
        processFrame(E0, O0, E1, O1,
                     sm + OFF_MCO + (t + 1) * 12,            // mag row f0+3 = 2t+3 (odd)
                     sm + OFF_SPE + t * 20);                  // P row f0 (even)
        if (f1 < NFR) {
            const float4 E2 = *reinterpret_cast<const float4*>(sm + OFF_WVE + (t + 2) * 4);
            // frame f1: groups f0+1..f0+4 = O t, E t+1, O t+1, E t+2
            processFrame(O0, E1, O1, E2,
                         sm + OFF_MCE + (t + 2) * 12,        // mag row f1+3 = 2t+4 (even)
                         sm + OFF_SPO + t * 20);              // P row f1 (odd)
        }
    }
    __syncthreads();

    // ---- Phase B2 (paired): pure overlap-add of P + env normalization ----
    const int ngO = nout >> 2;
    const int npO = (ngO + 1) >> 1;
    float* outb = out + (size_t)b * LOUT + s0;
    if (tid < npO) {
        const int t  = tid;
        const int g0 = 2 * t;
        const int g1 = g0 + 1;
        const int X0 = F0 + g0 + 2;
        const bool fast = (g1 < ngO) && (X0 - 3 >= TLO) && (X0 + 1 <= THI);
        if (fast) {
            const int Rb = X0 - TLO - 3;                    // row of frame X0-3
            const float* r0 = pRowPtr(sm, Rb);
            const float* r1 = pRowPtr(sm, Rb + 1);
            const float* r2 = pRowPtr(sm, Rb + 2);
            const float* r3 = pRowPtr(sm, Rb + 3);
            const float* r4 = pRowPtr(sm, Rb + 4);
            const float4 q3_0 = *reinterpret_cast<const float4*>(r0 + 12);
            const float4 q2_1 = *reinterpret_cast<const float4*>(r1 + 8);
            const float4 q3_1 = *reinterpret_cast<const float4*>(r1 + 12);
            const float4 q1_2 = *reinterpret_cast<const float4*>(r2 + 4);
            const float4 q2_2 = *reinterpret_cast<const float4*>(r2 + 8);
            const float4 q0_3 = *reinterpret_cast<const float4*>(r3);
            const float4 q1_3 = *reinterpret_cast<const float4*>(r3 + 4);
            const float4 q0_4 = *reinterpret_cast<const float4*>(r4);
            // group g0 (top frame X0): P[X0][q0]+P[X0-1][q1]+P[X0-2][q2]+P[X0-3][q3]
            float4 ya;
            ya.x = (q0_3.x + q1_2.x) + (q2_1.x + q3_0.x);
            ya.y = (q0_3.y + q1_2.y) + (q2_1.y + q3_0.y);
            ya.z = (q0_3.z + q1_2.z) + (q2_1.z + q3_0.z);
            ya.w = (q0_3.w + q1_2.w) + (q2_1.w + q3_0.w);
            float4 yb;
            yb.x = (q0_4.x + q1_3.x) + (q2_2.x + q3_1.x);
            yb.y = (q0_4.y + q1_3.y) + (q2_2.y + q3_1.y);
            yb.z = (q0_4.z + q1_3.z) + (q2_2.z + q3_1.z);
            yb.w = (q0_4.w + q1_3.w) + (q2_2.w + q3_1.w);
            float4* op = reinterpret_cast<float4*>(outb + 8 * t);
            op[0] = make_float4(ya.x * EINVc(0), ya.y * EINVc(1), ya.z * EINVc(2), ya.w * EINVc(3));
            op[1] = make_float4(yb.x * EINVc(0), yb.y * EINVc(1), yb.z * EINVc(2), yb.w * EINVc(3));
        } else {
            // Boundary fallback: clamped frames + edge env, reading P rows.
            for (int gi = 0; gi < 2; gi++) {
                const int g = g0 + gi;
                if (g >= ngO) break;
                for (int r = 0; r < 4; r++) {
                    const int s  = s0 + 4 * g + r;
                    const int p  = s + 8;
                    const int Xp = p >> 2;
                    const int rr = p & 3;
                    float acc = 0.f, env = 0.f;
                    for (int jj = 0; jj < 4; jj++) {
                        const int tt = Xp - jj;
                        if (tt < TLO || tt > THI) continue;
                        const int n = rr + 4 * jj;
                        const float w = W16T[n];
                        acc += pRowPtr(sm, tt - TLO)[n];
                        env = fmaf(w, w, env);
                    }
                    outb[4 * g + r] = acc / env;
                }
            }
        }
    }
}

// ---------------------------------------------------------------------------
extern "C" void kernel_launch(void* const* d_in, const int* in_sizes, int n_in,
                              void* d_out, int out_size)
{
    (void)in_sizes; (void)n_in; (void)out_size;
    const float* mag = (const float*)d_in[0];
    float* out = (float*)d_out;
    // Maximize the shared-memory carveout so 6 CTAs/SM can be resident
    // (37.1 KB static smem per CTA). Attribute set is idempotent and
    // capture-safe (not a stream operation).
    cudaFuncSetAttribute(glim_kernel, cudaFuncAttributePreferredSharedMemoryCarveout, 100);
    dim3 grid(NT, BATCH);
    glim_kernel<<<grid, NTHR>>>(mag, out);
}

// round 6
// speedup vs baseline: 1.1571x; 1.1571x over previous
#include <cuda_runtime.h>

// ---------------------------------------------------------------------------
// Problem constants
// ---------------------------------------------------------------------------
constexpr int TFR   = 65536;
constexpr int KB9   = 9;
constexpr int BATCH = 32;
constexpr int LOUT  = (TFR - 1) * 4;            // 262140

constexpr int OT   = 1000;                      // output samples per tile
constexpr int NT   = (LOUT + OT - 1) / OT;      // 263 tiles
constexpr int NTHR = 256;

// Shared layout (word offsets), simple linear rows.
// Strides 12 / 4 / 20 are conflict-free for LDS.128 when consecutive threads
// touch consecutive rows (offsets mod 32 hit all eight multiples of 4 per
// 8-lane wavefront phase).
constexpr int OFF_MAG = 0;                       // mag rows: 260 x 12
constexpr int OFF_WAV = 3120;                    // wav groups: 256 x 4
constexpr int OFF_P   = 4144;                    // P rows: 253 x 20
constexpr int SMWORDS = 4144 + 253 * 20;         // 9204 words = 36816 B

// ---------------------------------------------------------------------------
// Compile-time twiddles (all angles multiples of pi/8)
// ---------------------------------------------------------------------------
#define HD __host__ __device__ __forceinline__

HD constexpr float cos8c(int m) {
    m &= 15;
    const int mm = m & 7;
    const float v =
        (mm == 0) ?  1.0f :
        (mm == 1) ?  0.92387953251128674f :
        (mm == 2) ?  0.70710678118654752f :
        (mm == 3) ?  0.38268343236508977f :
        (mm == 4) ?  0.0f :
        (mm == 5) ? -0.38268343236508977f :
        (mm == 6) ? -0.70710678118654752f :
                    -0.92387953251128674f;
    return (m & 8) ? -v : v;
}
HD constexpr float sin8c(int m) { return cos8c(m + 12); }
HD constexpr float wwinc(int n) { return 0.5f - 0.5f * cos8c(n); }   // hann(16)
HD constexpr float CSc(int k, int n) { return ((k == 0) ? 1.0f : 2.0f) * 0.0625f * cos8c(k * n) * wwinc(n); }
HD constexpr float SNc(int k, int n) { return -2.0f * 0.0625f * sin8c(k * n) * wwinc(n); }
HD constexpr float envsum(int r) {
    return wwinc(r)      * wwinc(r)      + wwinc(r + 4)  * wwinc(r + 4)
         + wwinc(r + 8)  * wwinc(r + 8)  + wwinc(r + 12) * wwinc(r + 12);
}
HD constexpr float EINVc(int r) { return 1.0f / envsum(r); }
// env-folded coefficients (phase A fast path only)
HD constexpr float CSF(int k, int n) { return CSc(k, n) * EINVc(n & 3); }

// Runtime tables for rare edge-fallback paths
__constant__ float C8T[16] = { cos8c(0), cos8c(1), cos8c(2), cos8c(3), cos8c(4), cos8c(5), cos8c(6), cos8c(7),
                               cos8c(8), cos8c(9), cos8c(10), cos8c(11), cos8c(12), cos8c(13), cos8c(14), cos8c(15) };
__constant__ float W16T[16] = { wwinc(0), wwinc(1), wwinc(2), wwinc(3), wwinc(4), wwinc(5), wwinc(6), wwinc(7),
                                wwinc(8), wwinc(9), wwinc(10), wwinc(11), wwinc(12), wwinc(13), wwinc(14), wwinc(15) };

// ---------------------------------------------------------------------------
// Phase-A accumulator (env folded in; fully constant-folded)
// ---------------------------------------------------------------------------
template<int JJ>
__device__ __forceinline__ void accA(const float4 u0, const float4 u1, const float m4,
                                     float& y0, float& y1, float& y2, float& y3)
{
    { constexpr int n = 4 * JJ + 0;
      if (CSF(0,n) != 0.f) y0 = fmaf(u0.x, CSF(0,n), y0);
      if (CSF(1,n) != 0.f) y0 = fmaf(u0.y, CSF(1,n), y0);
      if (CSF(2,n) != 0.f) y0 = fmaf(u0.z, CSF(2,n), y0);
      if (CSF(3,n) != 0.f) y0 = fmaf(u0.w, CSF(3,n), y0);
      if (CSF(4,n) != 0.f) y0 = fmaf(m4,   CSF(4,n), y0); }
    { constexpr int n = 4 * JJ + 1;
      if (CSF(0,n) != 0.f) y1 = fmaf(u1.x, CSF(0,n), y1);
      if (CSF(1,n) != 0.f) y1 = fmaf(u1.y, CSF(1,n), y1);
      if (CSF(2,n) != 0.f) y1 = fmaf(u1.z, CSF(2,n), y1);
      if (CSF(3,n) != 0.f) y1 = fmaf(u1.w, CSF(3,n), y1); }
    { constexpr int n = 4 * JJ + 2;
      if (CSF(0,n) != 0.f) y2 = fmaf(u0.x, CSF(0,n), y2);
      if (CSF(1,n) != 0.f) y2 = fmaf(u0.y, CSF(1,n), y2);
      if (CSF(2,n) != 0.f) y2 = fmaf(u0.z, CSF(2,n), y2);
      if (CSF(3,n) != 0.f) y2 = fmaf(u0.w, CSF(3,n), y2);
      if (CSF(4,n) != 0.f) y2 = fmaf(m4,   CSF(4,n), y2); }
    { constexpr int n = 4 * JJ + 3;
      if (CSF(0,n) != 0.f) y3 = fmaf(u1.x, CSF(0,n), y3);
      if (CSF(1,n) != 0.f) y3 = fmaf(u1.y, CSF(1,n), y3);
      if (CSF(2,n) != 0.f) y3 = fmaf(u1.z, CSF(2,n), y3);
      if (CSF(3,n) != 0.f) y3 = fmaf(u1.w, CSF(3,n), y3); }
}

// P accumulator: per-frame windowed ISTFT samples, NO env folding.
template<int JJ>
__device__ __forceinline__ void accP(const float4 v0, const float4 v1, const float4 v2, const float4 v3,
                                     float& y0, float& y1, float& y2, float& y3)
{
    { constexpr int n = 4 * JJ + 0;
      if (CSc(0,n) != 0.f) y0 = fmaf(v0.x, CSc(0,n), y0);
      if (CSc(1,n) != 0.f) y0 = fmaf(v0.y, CSc(1,n), y0);
      if (CSc(2,n) != 0.f) y0 = fmaf(v0.z, CSc(2,n), y0);
      if (CSc(3,n) != 0.f) y0 = fmaf(v0.w, CSc(3,n), y0);
      if (CSc(4,n) != 0.f) y0 = fmaf(v3.w, CSc(4,n), y0);
      if (SNc(1,n) != 0.f) y0 = fmaf(v3.x, SNc(1,n), y0);
      if (SNc(2,n) != 0.f) y0 = fmaf(v3.y, SNc(2,n), y0);
      if (SNc(3,n) != 0.f) y0 = fmaf(v3.z, SNc(3,n), y0); }
    { constexpr int n = 4 * JJ + 1;
      if (CSc(0,n) != 0.f) y1 = fmaf(v1.x, CSc(0,n), y1);
      if (CSc(1,n) != 0.f) y1 = fmaf(v1.y, CSc(1,n), y1);
      if (CSc(2,n) != 0.f) y1 = fmaf(v1.z, CSc(2,n), y1);
      if (CSc(3,n) != 0.f) y1 = fmaf(v1.w, CSc(3,n), y1);
      if (SNc(1,n) != 0.f) y1 = fmaf(v2.x, SNc(1,n), y1);
      if (SNc(2,n) != 0.f) y1 = fmaf(v2.y, SNc(2,n), y1);
      if (SNc(3,n) != 0.f) y1 = fmaf(v2.z, SNc(3,n), y1);
      if (SNc(4,n) != 0.f) y1 = fmaf(v2.w, SNc(4,n), y1); }
    { constexpr int n = 4 * JJ + 2;
      if (CSc(0,n) != 0.f) y2 = fmaf(v0.x, CSc(0,n), y2);
      if (CSc(1,n) != 0.f) y2 = fmaf(v0.y, CSc(1,n), y2);
      if (CSc(2,n) != 0.f) y2 = fmaf(v0.z, CSc(2,n), y2);
      if (CSc(3,n) != 0.f) y2 = fmaf(v0.w, CSc(3,n), y2);
      if (CSc(4,n) != 0.f) y2 = fmaf(v3.w, CSc(4,n), y2);
      if (SNc(1,n) != 0.f) y2 = fmaf(v3.x, SNc(1,n), y2);
      if (SNc(2,n) != 0.f) y2 = fmaf(v3.y, SNc(2,n), y2);
      if (SNc(3,n) != 0.f) y2 = fmaf(v3.z, SNc(3,n), y2); }
    { constexpr int n = 4 * JJ + 3;
      if (CSc(0,n) != 0.f) y3 = fmaf(v1.x, CSc(0,n), y3);
      if (CSc(1,n) != 0.f) y3 = fmaf(v1.y, CSc(1,n), y3);
      if (CSc(2,n) != 0.f) y3 = fmaf(v1.z, CSc(2,n), y3);
      if (CSc(3,n) != 0.f) y3 = fmaf(v1.w, CSc(3,n), y3);
      if (SNc(1,n) != 0.f) y3 = fmaf(v2.x, SNc(1,n), y3);
      if (SNc(2,n) != 0.f) y3 = fmaf(v2.y, SNc(2,n), y3);
      if (SNc(3,n) != 0.f) y3 = fmaf(v2.z, SNc(3,n), y3);
      if (SNc(4,n) != 0.f) y3 = fmaf(v2.w, SNc(4,n), y3); }
}

// ---------------------------------------------------------------------------
__global__ void __launch_bounds__(NTHR, 6)
glim_kernel(const float* __restrict__ mag, float* __restrict__ out)
{
    __shared__ __align__(16) float sm[SMWORDS];

    const int tid  = threadIdx.x;
    const int b    = blockIdx.y;
    const int s0   = blockIdx.x * OT;
    const int nout = min(OT, LOUT - s0);
    const int F0   = s0 >> 2;
    const int TLO  = max(0, F0 - 1);
    const int THI  = min(TFR - 1, (s0 + nout + 7) >> 2);
    const int NFR  = THI - TLO + 1;
    const int tM0  = TLO - 3;
    const int ROWS = NFR + 7;

    const float* magb = mag + (size_t)b * (KB9 * TFR);

    // ---- stage: load bin pairs, store combined S/D + M4 ----
    #pragma unroll
    for (int pass = 0; pass < 2; pass++) {
        const int tt = tid + pass * NTHR;
        if (tt < ROWS) {
            const int tg = tM0 + tt;
            float4 S, D; float m4;
            if (tg >= 0 && tg < TFR) {
                const float* gp = magb + tg;
                const float a0 = __ldg(gp);            const float a8 = __ldg(gp + 8 * TFR);
                const float a1 = __ldg(gp + 1 * TFR);  const float a7 = __ldg(gp + 7 * TFR);
                const float a2 = __ldg(gp + 2 * TFR);  const float a6 = __ldg(gp + 6 * TFR);
                const float a3 = __ldg(gp + 3 * TFR);  const float a5 = __ldg(gp + 5 * TFR);
                m4 = __ldg(gp + 4 * TFR);
                S = make_float4(a0 + a8, a1 + a7, a2 + a6, a3 + a5);
                D = make_float4(a0 - a8, a1 - a7, a2 - a6, a3 - a5);
            } else {
                S = make_float4(0.f, 0.f, 0.f, 0.f);
                D = S; m4 = 0.f;
            }
            float* rp = sm + OFF_MAG + tt * 12;
            *reinterpret_cast<float4*>(rp)     = S;
            *reinterpret_cast<float4*>(rp + 4) = D;
            rp[8] = m4;
        }
    }
    __syncthreads();

    // ---- Phase A (unpaired): wav_i = ISTFT of zero-phase spectrum ----
    const int ngA = NFR + 3;
    if (tid < ngA) {
        const int g     = tid;
        const int jbase = 4 * TLO - 8 + 4 * g;
        const int X     = TLO + g;
        if (jbase >= 0 && jbase + 3 < LOUT && X >= 3 && X <= TFR - 1) {
            float y0 = 0.f, y1 = 0.f, y2 = 0.f, y3 = 0.f;
            const float* r0 = sm + OFF_MAG + g * 12;
            {   const float4 u0 = *reinterpret_cast<const float4*>(r0);
                const float4 u1 = *reinterpret_cast<const float4*>(r0 + 4);
                accA<3>(u0, u1, r0[8], y0, y1, y2, y3); }
            {   const float4 u0 = *reinterpret_cast<const float4*>(r0 + 12);
                const float4 u1 = *reinterpret_cast<const float4*>(r0 + 16);
                accA<2>(u0, u1, r0[20], y0, y1, y2, y3); }
            {   const float4 u0 = *reinterpret_cast<const float4*>(r0 + 24);
                const float4 u1 = *reinterpret_cast<const float4*>(r0 + 28);
                accA<1>(u0, u1, r0[32], y0, y1, y2, y3); }
            {   const float4 u0 = *reinterpret_cast<const float4*>(r0 + 36);
                const float4 u1 = *reinterpret_cast<const float4*>(r0 + 40);
                accA<0>(u0, u1, r0[44], y0, y1, y2, y3); }
            *reinterpret_cast<float4*>(sm + OFF_WAV + g * 4) = make_float4(y0, y1, y2, y3);
        } else {
            // Edge fallback: reflect + clamp + edge env (runtime tables)
            float* wp = sm + OFF_WAV + g * 4;
            for (int r = 0; r < 4; r++) {
                const int jg = jbase + r;
                const int jr = (jg < 0) ? -jg : ((jg >= LOUT) ? 2 * LOUT - 2 - jg : jg);
                const int p  = jr + 8;
                const int Xp = p >> 2;
                const int rr = p & 3;
                float acc = 0.f, env = 0.f;
                for (int jj = 0; jj < 4; jj++) {
                    const int tt = Xp - jj;
                    if (tt < 0 || tt >= TFR) continue;
                    const int n = rr + 4 * jj;
                    const float w = W16T[n];
                    const float* rp = sm + OFF_MAG + (tt - tM0) * 12;
                    float ssum;
                    if (n & 1) {
                        ssum = rp[4]
                             + 2.f * (rp[5] * C8T[n & 15] + rp[6] * C8T[(2 * n) & 15] + rp[7] * C8T[(3 * n) & 15]);
                    } else {
                        ssum = rp[0]
                             + 2.f * (rp[1] * C8T[n & 15] + rp[2] * C8T[(2 * n) & 15] + rp[3] * C8T[(3 * n) & 15]
                                    + rp[8] * C8T[(4 * n) & 15]);
                    }
                    acc = fmaf(ssum, 0.0625f * w, acc);
                    env = fmaf(w, w, env);
                }
                wp[r] = acc / env;
            }
        }
    }
    __syncthreads();

    // ---- Phase B1 (unpaired): rfft + normalize + frame ISTFT -> P row ----
    if (tid < NFR) {
        const int f = tid;
        const float4* w4 = reinterpret_cast<const float4*>(sm + OFF_WAV + f * 4);
        const float4 A0 = w4[0], A1 = w4[1], A2 = w4[2], A3 = w4[3];
        const float x1 = A0.y, x2 = A0.z, x3 = A0.w, x4 = A1.x, x5 = A1.y, x6 = A1.z, x7 = A1.w;
        const float x8 = A2.x, x9 = A2.y, x10 = A2.z, x11 = A2.w, x12 = A3.x, x13 = A3.y, x14 = A3.z, x15 = A3.w;

        float e[8], o[8];
        e[1] = wwinc(1) * (x1 + x15);  o[1] = wwinc(1) * (x1 - x15);
        e[2] = wwinc(2) * (x2 + x14);  o[2] = wwinc(2) * (x2 - x14);
        e[3] = wwinc(3) * (x3 + x13);  o[3] = wwinc(3) * (x3 - x13);
        e[4] = wwinc(4) * (x4 + x12);  o[4] = wwinc(4) * (x4 - x12);
        e[5] = wwinc(5) * (x5 + x11);  o[5] = wwinc(5) * (x5 - x11);
        e[6] = wwinc(6) * (x6 + x10);  o[6] = wwinc(6) * (x6 - x10);
        e[7] = wwinc(7) * (x7 + x9);   o[7] = wwinc(7) * (x7 - x9);

        // Magnitudes reconstructed from staged S/D (row f+3)
        const float* mrp = sm + OFF_MAG + (f + 3) * 12;
        const float4 MS = *reinterpret_cast<const float4*>(mrp);
        const float4 MD = *reinterpret_cast<const float4*>(mrp + 4);
        float mv[9];
        mv[0] = 0.5f * (MS.x + MD.x);  mv[8] = 0.5f * (MS.x - MD.x);
        mv[1] = 0.5f * (MS.y + MD.y);  mv[7] = 0.5f * (MS.y - MD.y);
        mv[2] = 0.5f * (MS.z + MD.z);  mv[6] = 0.5f * (MS.z - MD.z);
        mv[3] = 0.5f * (MS.w + MD.w);  mv[5] = 0.5f * (MS.w - MD.w);
        mv[4] = mrp[8];

        float ca[9], sa[9];
        #pragma unroll
        for (int k = 0; k < 9; k++) {
            float re = (k & 1) ? -x8 : x8;
            #pragma unroll
            for (int n = 1; n < 8; n++) {
                const float c = cos8c(k * n);
                if (c != 0.f) re = fmaf(e[n], c, re);
            }
            if (k == 0 || k == 8) {
                ca[k] = copysignf(mv[k], re);
                sa[k] = 0.f;
            } else {
                float im = 0.f;
                #pragma unroll
                for (int n = 1; n < 8; n++) {
                    const float ns = -sin8c(k * n);
                    if (ns != 0.f) im = fmaf(o[n], ns, im);
                }
                const float n2 = fmaf(re, re, im * im);
                if (n2 > 0.f) {
                    const float u = mv[k] * rsqrtf(n2);
                    ca[k] = re * u;
                    sa[k] = im * u;
                } else {
                    ca[k] = mv[k];
                    sa[k] = 0.f;
                }
            }
        }

        // Symmetric combos, then full 16-sample windowed frame ISTFT
        const float4 v0 = make_float4(ca[0] + ca[8], ca[1] + ca[7], ca[2] + ca[6], ca[3] + ca[5]);
        const float4 v1 = make_float4(ca[0] - ca[8], ca[1] - ca[7], ca[2] - ca[6], ca[3] - ca[5]);
        const float4 v2 = make_float4(sa[1] + sa[7], sa[2] + sa[6], sa[3] + sa[5], sa[4]);
        const float4 v3 = make_float4(sa[1] - sa[7], sa[2] - sa[6], sa[3] - sa[5], ca[4]);

        float* prow = sm + OFF_P + f * 20;
        {
            float p0 = 0.f, p1 = 0.f, p2 = 0.f, p3 = 0.f;
            accP<0>(v0, v1, v2, v3, p0, p1, p2, p3);
            *reinterpret_cast<float4*>(prow) = make_float4(p0, p1, p2, p3);
        }
        {
            float p0 = 0.f, p1 = 0.f, p2 = 0.f, p3 = 0.f;
            accP<1>(v0, v1, v2, v3, p0, p1, p2, p3);
            *reinterpret_cast<float4*>(prow + 4) = make_float4(p0, p1, p2, p3);
        }
        {
            float p0 = 0.f, p1 = 0.f, p2 = 0.f, p3 = 0.f;
            accP<2>(v0, v1, v2, v3, p0, p1, p2, p3);
            *reinterpret_cast<float4*>(prow + 8) = make_float4(p0, p1, p2, p3);
        }
        {
            float p0 = 0.f, p1 = 0.f, p2 = 0.f, p3 = 0.f;
            accP<3>(v0, v1, v2, v3, p0, p1, p2, p3);
            *reinterpret_cast<float4*>(prow + 12) = make_float4(p0, p1, p2, p3);
        }
    }
    __syncthreads();

    // ---- Phase B2 (unpaired): pure overlap-add of P + env normalization ----
    const int ngO = nout >> 2;
    float* outb = out + (size_t)b * LOUT + s0;
    if (tid < ngO) {
        const int g = tid;
        const int X = F0 + g + 2;
        if (X - 3 >= TLO && X <= THI) {
            const int Rb = X - TLO - 3;                    // row of frame X-3
            const float* r0 = sm + OFF_P + Rb * 20;
            const float4 q3 = *reinterpret_cast<const float4*>(r0 + 12);        // frame X-3, n=12..15
            const float4 q2 = *reinterpret_cast<const float4*>(r0 + 20 + 8);    // frame X-2, n=8..11
            const float4 q1 = *reinterpret_cast<const float4*>(r0 + 40 + 4);    // frame X-1, n=4..7
            const float4 q0 = *reinterpret_cast<const float4*>(r0 + 60);        // frame X,   n=0..3
            float4 y;
            y.x = ((q0.x + q1.x) + (q2.x + q3.x)) * EINVc(0);
            y.y = ((q0.y + q1.y) + (q2.y + q3.y)) * EINVc(1);
            y.z = ((q0.z + q1.z) + (q2.z + q3.z)) * EINVc(2);
            y.w = ((q0.w + q1.w) + (q2.w + q3.w)) * EINVc(3);
            *reinterpret_cast<float4*>(outb + 4 * g) = y;
        } else {
            // Boundary fallback: clamped frames + edge env, reading P rows.
            for (int r = 0; r < 4; r++) {
                const int s  = s0 + 4 * g + r;
                const int p  = s + 8;
                const int Xp = p >> 2;
                const int rr = p & 3;
                float acc = 0.f, env = 0.f;
                for (int jj = 0; jj < 4; jj++) {
                    const int tt = Xp - jj;
                    if (tt < TLO || tt > THI) continue;
                    const int n = rr + 4 * jj;
                    const float w = W16T[n];
                    acc += sm[OFF_P + (tt - TLO) * 20 + n];
                    env = fmaf(w, w, env);
                }
                outb[4 * g + r] = acc / env;
            }
        }
    }
}

// ---------------------------------------------------------------------------
extern "C" void kernel_launch(void* const* d_in, const int* in_sizes, int n_in,
                              void* d_out, int out_size)
{
    (void)in_sizes; (void)n_in; (void)out_size;
    const float* mag = (const float*)d_in[0];
    float* out = (float*)d_out;
    // Maximize shared carveout so 6 CTAs/SM (36.8 KB each) can be resident.
    cudaFuncSetAttribute(glim_kernel, cudaFuncAttributePreferredSharedMemoryCarveout, 100);
    dim3 grid(NT, BATCH);
    glim_kernel<<<grid, NTHR>>>(mag, out);
}

// round 7
// speedup vs baseline: 1.2139x; 1.0491x over previous
#include <cuda_runtime.h>

// ---------------------------------------------------------------------------
// Problem constants
// ---------------------------------------------------------------------------
constexpr int TFR   = 65536;
constexpr int KB9   = 9;
constexpr int BATCH = 32;
constexpr int LOUT  = (TFR - 1) * 4;            // 262140

constexpr int OT   = 1000;                      // output samples per tile
constexpr int NT   = (LOUT + OT - 1) / OT;      // 263 tiles
constexpr int NTHR = 256;

// Shared layout (word offsets), simple linear rows.
constexpr int OFF_MAG = 0;                       // mag rows: 260 x 12
constexpr int OFF_WAV = 3120;                    // wav groups: 256 x 4
constexpr int OFF_P   = 4144;                    // P rows: 253 x 20
constexpr int SMWORDS = 4144 + 253 * 20;         // 9204 words = 36816 B

// ---------------------------------------------------------------------------
// Compile-time twiddles (all angles multiples of pi/8)
// ---------------------------------------------------------------------------
#define HD __host__ __device__ __forceinline__

HD constexpr float cos8c(int m) {
    m &= 15;
    const int mm = m & 7;
    const float v =
        (mm == 0) ?  1.0f :
        (mm == 1) ?  0.92387953251128674f :
        (mm == 2) ?  0.70710678118654752f :
        (mm == 3) ?  0.38268343236508977f :
        (mm == 4) ?  0.0f :
        (mm == 5) ? -0.38268343236508977f :
        (mm == 6) ? -0.70710678118654752f :
                    -0.92387953251128674f;
    return (m & 8) ? -v : v;
}
HD constexpr float sin8c(int m) { return cos8c(m + 12); }
HD constexpr float wwinc(int n) { return 0.5f - 0.5f * cos8c(n); }   // hann(16)
HD constexpr float CSc(int k, int n) { return ((k == 0) ? 1.0f : 2.0f) * 0.0625f * cos8c(k * n) * wwinc(n); }
HD constexpr float envsum(int r) {
    return wwinc(r)      * wwinc(r)      + wwinc(r + 4)  * wwinc(r + 4)
         + wwinc(r + 8)  * wwinc(r + 8)  + wwinc(r + 12) * wwinc(r + 12);
}
HD constexpr float EINVc(int r) { return 1.0f / envsum(r); }
HD constexpr float CSF(int k, int n) { return CSc(k, n) * EINVc(n & 3); }
HD constexpr float W8c(int n) { return wwinc(n) * 0.125f; }          // window/8 for P rows

// Runtime tables for rare edge-fallback paths
__constant__ float C8T[16] = { cos8c(0), cos8c(1), cos8c(2), cos8c(3), cos8c(4), cos8c(5), cos8c(6), cos8c(7),
                               cos8c(8), cos8c(9), cos8c(10), cos8c(11), cos8c(12), cos8c(13), cos8c(14), cos8c(15) };
__constant__ float W16T[16] = { wwinc(0), wwinc(1), wwinc(2), wwinc(3), wwinc(4), wwinc(5), wwinc(6), wwinc(7),
                                wwinc(8), wwinc(9), wwinc(10), wwinc(11), wwinc(12), wwinc(13), wwinc(14), wwinc(15) };

// ---------------------------------------------------------------------------
// Phase-A accumulator (env folded in; fully constant-folded)
// ---------------------------------------------------------------------------
template<int JJ>
__device__ __forceinline__ void accA(const float4 u0, const float4 u1, const float m4,
                                     float& y0, float& y1, float& y2, float& y3)
{
    { constexpr int n = 4 * JJ + 0;
      if (CSF(0,n) != 0.f) y0 = fmaf(u0.x, CSF(0,n), y0);
      if (CSF(1,n) != 0.f) y0 = fmaf(u0.y, CSF(1,n), y0);
      if (CSF(2,n) != 0.f) y0 = fmaf(u0.z, CSF(2,n), y0);
      if (CSF(3,n) != 0.f) y0 = fmaf(u0.w, CSF(3,n), y0);
      if (CSF(4,n) != 0.f) y0 = fmaf(m4,   CSF(4,n), y0); }
    { constexpr int n = 4 * JJ + 1;
      if (CSF(0,n) != 0.f) y1 = fmaf(u1.x, CSF(0,n), y1);
      if (CSF(1,n) != 0.f) y1 = fmaf(u1.y, CSF(1,n), y1);
      if (CSF(2,n) != 0.f) y1 = fmaf(u1.z, CSF(2,n), y1);
      if (CSF(3,n) != 0.f) y1 = fmaf(u1.w, CSF(3,n), y1); }
    { constexpr int n = 4 * JJ + 2;
      if (CSF(0,n) != 0.f) y2 = fmaf(u0.x, CSF(0,n), y2);
      if (CSF(1,n) != 0.f) y2 = fmaf(u0.y, CSF(1,n), y2);
      if (CSF(2,n) != 0.f) y2 = fmaf(u0.z, CSF(2,n), y2);
      if (CSF(3,n) != 0.f) y2 = fmaf(u0.w, CSF(3,n), y2);
      if (CSF(4,n) != 0.f) y2 = fmaf(m4,   CSF(4,n), y2); }
    { constexpr int n = 4 * JJ + 3;
      if (CSF(0,n) != 0.f) y3 = fmaf(u1.x, CSF(0,n), y3);
      if (CSF(1,n) != 0.f) y3 = fmaf(u1.y, CSF(1,n), y3);
      if (CSF(2,n) != 0.f) y3 = fmaf(u1.z, CSF(2,n), y3);
      if (CSF(3,n) != 0.f) y3 = fmaf(u1.w, CSF(3,n), y3); }
}

// ---------------------------------------------------------------------------
// B1 frame processing, FFT-folded:
//   forward: window fold (n<->16-n), then n<->8-n fold + (k,8-k) CSE
//   inverse: k<->8-k combos + n<->16-n pair fold + E/O CSE
// ---------------------------------------------------------------------------
__device__ __forceinline__ void processFrame(const float4 A0, const float4 A1,
                                             const float4 A2, const float4 A3,
                                             const float* __restrict__ mrp,
                                             float* __restrict__ prow)
{
    constexpr float c1 = 0.92387953251128674f;   // cos(pi/8)
    constexpr float c2 = 0.70710678118654752f;   // cos(pi/4)
    constexpr float c3 = 0.38268343236508977f;   // cos(3pi/8)

    const float x8 = A2.x;
    // window + first fold: e_n = w_n(x_n + x_{16-n}), o_n = w_n(x_n - x_{16-n})
    const float e1 = wwinc(1) * (A0.y + A3.w), o1 = wwinc(1) * (A0.y - A3.w);
    const float e2 = wwinc(2) * (A0.z + A3.z), o2 = wwinc(2) * (A0.z - A3.z);
    const float e3 = wwinc(3) * (A0.w + A3.y), o3 = wwinc(3) * (A0.w - A3.y);
    const float e4 = wwinc(4) * (A1.x + A3.x), o4 = wwinc(4) * (A1.x - A3.x);
    const float e5 = wwinc(5) * (A1.y + A2.w), o5 = wwinc(5) * (A1.y - A2.w);
    const float e6 = wwinc(6) * (A1.z + A2.z), o6 = wwinc(6) * (A1.z - A2.z);
    const float e7 = wwinc(7) * (A1.w + A2.y), o7 = wwinc(7) * (A1.w - A2.y);

    // second fold n<->8-n
    const float es1 = e1 + e7, es2 = e2 + e6, es3 = e3 + e5;
    const float ed1 = e1 - e7, ed2 = e2 - e6, ed3 = e3 - e5;
    const float os1 = o1 + o7, os2 = o2 + o6, os3 = o3 + o5;
    const float od1 = o1 - o7, od2 = o2 - o6, od3 = o3 - o5;

    float re[9], im[9];
    {   // even-k re: re_k = x8 + sum es_n cos(kn pi/8) + e4 cos(k pi/2)
        const float t1 = c2 * (es1 - es3);
        const float t2 = x8 - e4, t3 = x8 + e4;
        const float q  = es1 + es3;
        const float Aa = t3 + es2;
        re[0] = Aa + q;  re[8] = Aa - q;
        re[2] = t2 + t1; re[6] = t2 - t1;
        re[4] = t3 - es2;
    }
    {   // odd-k re: re_k = -x8 + sum ed_n cos(kn pi/8)
        const float m  = ed2 * c2;
        const float v  = m - x8, w = -m - x8;
        const float u  = fmaf(ed1, c1,  ed3 * c3);     // ed1*c1 + ed3*c3
        const float u2 = fmaf(ed1, c3, -(ed3 * c1));   // ed1*c3 - ed3*c1
        re[1] = v + u;  re[7] = v - u;
        re[3] = w + u2; re[5] = w - u2;
    }
    {   // odd-k im: im_k = -[ sum os_n sin(kn pi/8) + o4*(+-1) ]
        const float a  = fmaf(os1, c3,  os3 * c1);
        const float b  = fmaf(os2, c2,  o4);
        const float a2 = fmaf(os1, c1, -(os3 * c3));
        const float b2 = fmaf(os2, c2, -o4);
        im[1] = -(a + b);   im[3] = -(a2 + b2);
        im[5] = b2 - a2;    im[7] = b - a;
    }
    {   // even-k im (from od_n; o4 term vanishes)
        const float t4 = c2 * (od1 + od3);
        im[2] = -(t4 + od2); im[6] = od2 - t4; im[4] = od3 - od1;
    }

    // magnitudes reconstructed from staged S/D
    const float4 MS = *reinterpret_cast<const float4*>(mrp);
    const float4 MD = *reinterpret_cast<const float4*>(mrp + 4);
    float mv[9];
    mv[0] = 0.5f * (MS.x + MD.x);  mv[8] = 0.5f * (MS.x - MD.x);
    mv[1] = 0.5f * (MS.y + MD.y);  mv[7] = 0.5f * (MS.y - MD.y);
    mv[2] = 0.5f * (MS.z + MD.z);  mv[6] = 0.5f * (MS.z - MD.z);
    mv[3] = 0.5f * (MS.w + MD.w);  mv[5] = 0.5f * (MS.w - MD.w);
    mv[4] = mrp[8];

    // phase normalization
    float ca[9], sa[9];
    ca[0] = copysignf(mv[0], re[0]);
    ca[8] = copysignf(mv[8], re[8]);
    #pragma unroll
    for (int k = 1; k < 8; k++) {
        const float n2 = fmaf(re[k], re[k], im[k] * im[k]);
        if (n2 > 0.f) {
            const float u = mv[k] * rsqrtf(n2);
            ca[k] = re[k] * u;
            sa[k] = im[k] * u;
        } else {
            ca[k] = mv[k];
            sa[k] = 0.f;
        }
    }

    // inverse: k<->8-k combos
    const float Ai1 = ca[1] + ca[7], Ai2 = ca[2] + ca[6], Ai3 = ca[3] + ca[5];
    const float Ci1 = ca[1] - ca[7], Ci2 = ca[2] - ca[6], Ci3 = ca[3] - ca[5];
    const float Si1 = sa[1] + sa[7], Si2 = sa[2] + sa[6], Si3 = sa[3] + sa[5];
    const float Di1 = sa[1] - sa[7], Di2 = sa[2] - sa[6], Di3 = sa[3] - sa[5];
    const float z2  = 0.5f * (ca[0] + ca[8]);
    const float z2p = 0.5f * (ca[0] - ca[8]);
    const float ca4 = ca[4], sa4 = sa[4];

    // even n (pairs (2,14),(4,12),(6,10) via s_{16-n} = E + O, s_n = E - O; n=8 alone)
    const float h1 = c2 * (Ai1 - Ai3);
    const float h2 = c2 * (Di1 + Di3);
    const float za = z2 - ca4, zb = z2 + ca4;
    const float E2 = za + h1, E6 = za - h1, E4 = zb - Ai2;
    const float O2 = h2 + Di2, O6 = h2 - Di2, O4 = Di1 - Di3;
    const float s8  = (zb + Ai2) - (Ai1 + Ai3);
    const float s2  = E2 - O2, s14 = E2 + O2;
    const float s4  = E4 - O4, s12 = E4 + O4;
    const float s6  = E6 - O6, s10 = E6 + O6;

    // odd n (pairs (1,15),(3,13),(5,11),(7,9))
    const float mC  = Ci2 * c2;
    const float uE  = fmaf(Ci1, c1,  Ci3 * c3);
    const float u2E = fmaf(Ci1, c3, -(Ci3 * c1));
    const float ta  = z2p + mC, tb = z2p - mC;
    const float E1 = ta + uE, E7 = ta - uE, E3 = tb + u2E, E5 = tb - u2E;
    const float nS  = Si2 * c2;
    const float vO  = fmaf(Si1, c3,  Si3 * c1);
    const float v2O = fmaf(Si1, c1, -(Si3 * c3));
    const float wo = nS + sa4, w2o = nS - sa4;
    const float O1 = vO + wo, O7 = vO - wo, O3 = v2O + w2o, O5 = v2O - w2o;
    const float s1  = E1 - O1, s15 = E1 + O1;
    const float s3  = E3 - O3, s13 = E3 + O3;
    const float s5  = E5 - O5, s11 = E5 + O5;
    const float s7  = E7 - O7, s9  = E7 + O7;

    // window/8 + store (P_0 = 0 since w(0) = 0)
    *reinterpret_cast<float4*>(prow)      = make_float4(0.f,        W8c(1)*s1,  W8c(2)*s2,   W8c(3)*s3);
    *reinterpret_cast<float4*>(prow + 4)  = make_float4(W8c(4)*s4,  W8c(5)*s5,  W8c(6)*s6,   W8c(7)*s7);
    *reinterpret_cast<float4*>(prow + 8)  = make_float4(W8c(8)*s8,  W8c(9)*s9,  W8c(10)*s10, W8c(11)*s11);
    *reinterpret_cast<float4*>(prow + 12) = make_float4(W8c(12)*s12, W8c(13)*s13, W8c(14)*s14, W8c(15)*s15);
}

// ---------------------------------------------------------------------------
__global__ void __launch_bounds__(NTHR, 6)
glim_kernel(const float* __restrict__ mag, float* __restrict__ out)
{
    __shared__ __align__(16) float sm[SMWORDS];

    const int tid  = threadIdx.x;
    const int b    = blockIdx.y;
    const int s0   = blockIdx.x * OT;
    const int nout = min(OT, LOUT - s0);
    const int F0   = s0 >> 2;
    const int TLO  = max(0, F0 - 1);
    const int THI  = min(TFR - 1, (s0 + nout + 7) >> 2);
    const int NFR  = THI - TLO + 1;
    const int tM0  = TLO - 3;
    const int ROWS = NFR + 7;

    const float* magb = mag + (size_t)b * (KB9 * TFR);

    // ---- stage: load bin pairs, store combined S/D + M4 ----
    #pragma unroll
    for (int pass = 0; pass < 2; pass++) {
        const int tt = tid + pass * NTHR;
        if (tt < ROWS) {
            const int tg = tM0 + tt;
            float4 S, D; float m4;
            if (tg >= 0 && tg < TFR) {
                const float* gp = magb + tg;
                const float a0 = __ldg(gp);            const float a8 = __ldg(gp + 8 * TFR);
                const float a1 = __ldg(gp + 1 * TFR);  const float a7 = __ldg(gp + 7 * TFR);
                const float a2 = __ldg(gp + 2 * TFR);  const float a6 = __ldg(gp + 6 * TFR);
                const float a3 = __ldg(gp + 3 * TFR);  const float a5 = __ldg(gp + 5 * TFR);
                m4 = __ldg(gp + 4 * TFR);
                S = make_float4(a0 + a8, a1 + a7, a2 + a6, a3 + a5);
                D = make_float4(a0 - a8, a1 - a7, a2 - a6, a3 - a5);
            } else {
                S = make_float4(0.f, 0.f, 0.f, 0.f);
                D = S; m4 = 0.f;
            }
            float* rp = sm + OFF_MAG + tt * 12;
            *reinterpret_cast<float4*>(rp)     = S;
            *reinterpret_cast<float4*>(rp + 4) = D;
            rp[8] = m4;
        }
    }
    __syncthreads();

    // ---- Phase A: wav_i = ISTFT of zero-phase spectrum ----
    const int ngA = NFR + 3;
    if (tid < ngA) {
        const int g     = tid;
        const int jbase = 4 * TLO - 8 + 4 * g;
        const int X     = TLO + g;
        if (jbase >= 0 && jbase + 3 < LOUT && X >= 3 && X <= TFR - 1) {
            float y0 = 0.f, y1 = 0.f, y2 = 0.f, y3 = 0.f;
            const float* r0 = sm + OFF_MAG + g * 12;
            {   const float4 u0 = *reinterpret_cast<const float4*>(r0);
                const float4 u1 = *reinterpret_cast<const float4*>(r0 + 4);
                accA<3>(u0, u1, r0[8], y0, y1, y2, y3); }
            {   const float4 u0 = *reinterpret_cast<const float4*>(r0 + 12);
                const float4 u1 = *reinterpret_cast<const float4*>(r0 + 16);
                accA<2>(u0, u1, r0[20], y0, y1, y2, y3); }
            {   const float4 u0 = *reinterpret_cast<const float4*>(r0 + 24);
                const float4 u1 = *reinterpret_cast<const float4*>(r0 + 28);
                accA<1>(u0, u1, r0[32], y0, y1, y2, y3); }
            {   const float4 u0 = *reinterpret_cast<const float4*>(r0 + 36);
                const float4 u1 = *reinterpret_cast<const float4*>(r0 + 40);
                accA<0>(u0, u1, r0[44], y0, y1, y2, y3); }
            *reinterpret_cast<float4*>(sm + OFF_WAV + g * 4) = make_float4(y0, y1, y2, y3);
        } else {
            // Edge fallback: reflect + clamp + edge env (runtime tables)
            float* wp = sm + OFF_WAV + g * 4;
            for (int r = 0; r < 4; r++) {
                const int jg = jbase + r;
                const int jr = (jg < 0) ? -jg : ((jg >= LOUT) ? 2 * LOUT - 2 - jg : jg);
                const int p  = jr + 8;
                const int Xp = p >> 2;
                const int rr = p & 3;
                float acc = 0.f, env = 0.f;
                for (int jj = 0; jj < 4; jj++) {
                    const int tt = Xp - jj;
                    if (tt < 0 || tt >= TFR) continue;
                    const int n = rr + 4 * jj;
                    const float w = W16T[n];
                    const float* rp = sm + OFF_MAG + (tt - tM0) * 12;
                    float ssum;
                    if (n & 1) {
                        ssum = rp[4]
                             + 2.f * (rp[5] * C8T[n & 15] + rp[6] * C8T[(2 * n) & 15] + rp[7] * C8T[(3 * n) & 15]);
                    } else {
                        ssum = rp[0]
                             + 2.f * (rp[1] * C8T[n & 15] + rp[2] * C8T[(2 * n) & 15] + rp[3] * C8T[(3 * n) & 15]
                                    + rp[8] * C8T[(4 * n) & 15]);
                    }
                    acc = fmaf(ssum, 0.0625f * w, acc);
                    env = fmaf(w, w, env);
                }
                wp[r] = acc / env;
            }
        }
    }
    __syncthreads();

    // ---- Phase B1: folded rfft + normalize + folded frame ISTFT -> P row ----
    if (tid < NFR) {
        const int f = tid;
        const float4* w4 = reinterpret_cast<const float4*>(sm + OFF_WAV + f * 4);
        processFrame(w4[0], w4[1], w4[2], w4[3],
                     sm + OFF_MAG + (f + 3) * 12,
                     sm + OFF_P + f * 20);
    }
    __syncthreads();

    // ---- Phase B2: pure overlap-add of P + env normalization ----
    const int ngO = nout >> 2;
    float* outb = out + (size_t)b * LOUT + s0;
    if (tid < ngO) {
        const int g = tid;
        const int X = F0 + g + 2;
        if (X - 3 >= TLO && X <= THI) {
            const int Rb = X - TLO - 3;
            const float* r0 = sm + OFF_P + Rb * 20;
            const float4 q3 = *reinterpret_cast<const float4*>(r0 + 12);        // frame X-3, n=12..15
            const float4 q2 = *reinterpret_cast<const float4*>(r0 + 20 + 8);    // frame X-2, n=8..11
            const float4 q1 = *reinterpret_cast<const float4*>(r0 + 40 + 4);    // frame X-1, n=4..7
            const float4 q0 = *reinterpret_cast<const float4*>(r0 + 60);        // frame X,   n=0..3
            float4 y;
            y.x = ((q0.x + q1.x) + (q2.x + q3.x)) * EINVc(0);
            y.y = ((q0.y + q1.y) + (q2.y + q3.y)) * EINVc(1);
            y.z = ((q0.z + q1.z) + (q2.z + q3.z)) * EINVc(2);
            y.w = ((q0.w + q1.w) + (q2.w + q3.w)) * EINVc(3);
            *reinterpret_cast<float4*>(outb + 4 * g) = y;
        } else {
            // Boundary fallback: clamped frames + edge env, reading P rows.
            for (int r = 0; r < 4; r++) {
                const int s  = s0 + 4 * g + r;
                const int p  = s + 8;
                const int Xp = p >> 2;
                const int rr = p & 3;
                float acc = 0.f, env = 0.f;
                for (int jj = 0; jj < 4; jj++) {
                    const int tt = Xp - jj;
                    if (tt < TLO || tt > THI) continue;
                    const int n = rr + 4 * jj;
                    const float w = W16T[n];
                    acc += sm[OFF_P + (tt - TLO) * 20 + n];
                    env = fmaf(w, w, env);
                }
                outb[4 * g + r] = acc / env;
            }
        }
    }
}

// ---------------------------------------------------------------------------
extern "C" void kernel_launch(void* const* d_in, const int* in_sizes, int n_in,
                              void* d_out, int out_size)
{
    (void)in_sizes; (void)n_in; (void)out_size;
    const float* mag = (const float*)d_in[0];
    float* out = (float*)d_out;
    // Maximize shared carveout so 6 CTAs/SM (36.8 KB each) can be resident.
    cudaFuncSetAttribute(glim_kernel, cudaFuncAttributePreferredSharedMemoryCarveout, 100);
    dim3 grid(NT, BATCH);
    glim_kernel<<<grid, NTHR>>>(mag, out);
}